// round 1
// baseline (speedup 1.0000x reference)
#include <cuda_runtime.h>
#include <cstdint>

// ---------------------------------------------------------------------------
// Policy_Network: dead-code-eliminated MLP chain.
//   ctx = [state(4096) | task(4) | action(1024)]  -> [8192, 5124]
//   x1 = ctx @ W_l1 + b_l1                         [8192, 2048]
//   x2 = [x1|ctx] @ W_l2 + b_l2                    [8192, 1024]
//   x3 = [x2|ctx] @ W_l3 + b_l3                    [8192, 1024]
//   x4 = [x3|ctx] @ W_l4 + b_l4                    [8192, 512]
//   out= x4 @ W_l5 + b_l5                          [8192, 1024]
// cx1..cx4 branches are dead (kwta == identity) and skipped.
// ---------------------------------------------------------------------------

#define BATCH   8192
#define NSTATE  4096
#define NTASK   4
#define NACT    1024
#define INPUTW  5124   // 4096 + 4 + 1024

// Scratch (device globals: no allocation allowed)
__device__ float g_ctx[(size_t)BATCH * INPUTW];   // 168 MB
__device__ float g_x1 [(size_t)BATCH * 2048];     // 64 MB
__device__ float g_x2 [(size_t)BATCH * 1024];     // 32 MB
__device__ float g_x3 [(size_t)BATCH * 1024];     // 32 MB
__device__ float g_x4 [(size_t)BATCH * 512];      // 16 MB

// ---------------------------------------------------------------------------
// Build ctx: one block per row, vectorized copies.
// Row layout offsets: state @0 (4096), task @4096 (4), action @4100 (1024).
// 4100*4B = 16400B is 16B-aligned, so float4 stores are legal for action part.
// ---------------------------------------------------------------------------
__global__ void build_ctx_kernel(const float* __restrict__ state,
                                 const float* __restrict__ task,
                                 const float* __restrict__ action) {
    int r = blockIdx.x;
    int t = threadIdx.x;  // 256 threads
    float* dst = g_ctx + (size_t)r * INPUTW;
    float4* d4 = reinterpret_cast<float4*>(dst);

    const float4* s4 = reinterpret_cast<const float4*>(state + (size_t)r * NSTATE);
    #pragma unroll
    for (int i = t; i < NSTATE / 4; i += 256) d4[i] = s4[i];

    if (t < NTASK) dst[NSTATE + t] = task[(size_t)r * NTASK + t];

    const float4* a4 = reinterpret_cast<const float4*>(action + (size_t)r * NACT);
    #pragma unroll
    for (int i = t; i < NACT / 4; i += 256) d4[(NSTATE + NTASK) / 4 + i] = a4[i];
}

// ---------------------------------------------------------------------------
// SGEMM with implicit concat:  C[M,N] = [A1 (K1 cols) | A2 (K2 cols)] @ W + b
// W is [(K1+K2), N] row-major. A1/A2 row strides == their widths.
// Tiles: 128x128 block, BK=16, 256 threads, 8x8 per-thread microtile.
// K1 is always a multiple of 16 here (2048/1024/1024), so each 16-wide k-tile
// is entirely inside A1 or A2. Ktot % 16 == 4 is handled by zero-fill guards
// (guards are per-float4; Ktot % 4 == 0 always).
// ---------------------------------------------------------------------------
__global__ __launch_bounds__(256, 2)
void sgemm_bias_concat(const float* __restrict__ A1, int K1,
                       const float* __restrict__ A2, int K2,
                       const float* __restrict__ W,
                       const float* __restrict__ bias,
                       float* __restrict__ C, int N) {
    const int Ktot = K1 + K2;

    __shared__ float As[16][132];  // transposed A tile, padded
    __shared__ float Bs[16][128];

    const int tid = threadIdx.x;
    const int tx = tid & 15;        // 0..15 -> 8 output cols each
    const int ty = tid >> 4;        // 0..15 -> 8 output rows each
    const int block_row = blockIdx.y * 128;
    const int block_col = blockIdx.x * 128;

    // A-load mapping: 512 float4 per tile / 256 thr = 2 each
    const int a_row  = tid >> 2;          // 0..63 (+64 second half)
    const int a_col4 = (tid & 3) << 2;    // 0,4,8,12
    // B-load mapping: 512 float4 per tile / 256 thr = 2 each
    const int b_row = tid >> 5;           // 0..7 (+8 second half)
    const int b_col = (tid & 31) << 2;    // 0..124

    float acc[8][8];
    #pragma unroll
    for (int i = 0; i < 8; i++)
        #pragma unroll
        for (int j = 0; j < 8; j++) acc[i][j] = 0.0f;

    for (int k0 = 0; k0 < Ktot; k0 += 16) {
        // ---- load A tile (transposed into As[k][m]) ----
        #pragma unroll
        for (int half = 0; half < 2; half++) {
            const int m = block_row + a_row + half * 64;
            const int k = k0 + a_col4;
            float4 v = make_float4(0.f, 0.f, 0.f, 0.f);
            if (k < Ktot) {
                if (k < K1) {
                    v = *reinterpret_cast<const float4*>(A1 + (size_t)m * K1 + k);
                } else {
                    v = *reinterpret_cast<const float4*>(A2 + (size_t)m * K2 + (k - K1));
                }
            }
            const int mm = a_row + half * 64;
            As[a_col4 + 0][mm] = v.x;
            As[a_col4 + 1][mm] = v.y;
            As[a_col4 + 2][mm] = v.z;
            As[a_col4 + 3][mm] = v.w;
        }
        // ---- load B tile ----
        #pragma unroll
        for (int half = 0; half < 2; half++) {
            const int k = k0 + b_row + half * 8;
            float4 v = make_float4(0.f, 0.f, 0.f, 0.f);
            if (k < Ktot) {
                v = *reinterpret_cast<const float4*>(W + (size_t)k * N + block_col + b_col);
            }
            *reinterpret_cast<float4*>(&Bs[b_row + half * 8][b_col]) = v;
        }
        __syncthreads();

        // ---- compute ----
        #pragma unroll
        for (int kk = 0; kk < 16; kk++) {
            float4 a0 = *reinterpret_cast<const float4*>(&As[kk][ty * 8]);
            float4 a1 = *reinterpret_cast<const float4*>(&As[kk][ty * 8 + 4]);
            float4 b0 = *reinterpret_cast<const float4*>(&Bs[kk][tx * 8]);
            float4 b1 = *reinterpret_cast<const float4*>(&Bs[kk][tx * 8 + 4]);
            float a[8] = {a0.x, a0.y, a0.z, a0.w, a1.x, a1.y, a1.z, a1.w};
            float b[8] = {b0.x, b0.y, b0.z, b0.w, b1.x, b1.y, b1.z, b1.w};
            #pragma unroll
            for (int i = 0; i < 8; i++)
                #pragma unroll
                for (int j = 0; j < 8; j++)
                    acc[i][j] = fmaf(a[i], b[j], acc[i][j]);
        }
        __syncthreads();
    }

    // ---- epilogue: add bias, store ----
    float bv[8];
    #pragma unroll
    for (int j = 0; j < 8; j++) bv[j] = bias[block_col + tx * 8 + j];

    #pragma unroll
    for (int i = 0; i < 8; i++) {
        const int m = block_row + ty * 8 + i;
        float* crow = C + (size_t)m * N + block_col + tx * 8;
        float4 o0, o1;
        o0.x = acc[i][0] + bv[0]; o0.y = acc[i][1] + bv[1];
        o0.z = acc[i][2] + bv[2]; o0.w = acc[i][3] + bv[3];
        o1.x = acc[i][4] + bv[4]; o1.y = acc[i][5] + bv[5];
        o1.z = acc[i][6] + bv[6]; o1.w = acc[i][7] + bv[7];
        *reinterpret_cast<float4*>(crow)     = o0;
        *reinterpret_cast<float4*>(crow + 4) = o1;
    }
}

// ---------------------------------------------------------------------------
// Host launcher
// ---------------------------------------------------------------------------
static float* sym_addr(const void* symbol) {
    void* p = nullptr;
    cudaGetSymbolAddress(&p, symbol);
    return reinterpret_cast<float*>(p);
}

extern "C" void kernel_launch(void* const* d_in, const int* in_sizes, int n_in,
                              void* d_out, int out_size) {
    const float* state  = (const float*)d_in[0];
    const float* action = (const float*)d_in[1];
    const float* task   = (const float*)d_in[2];
    // cx weights (d_in[3..18]) are dead -> unused.
    const float* W_l1 = (const float*)d_in[19];
    const float* b_l1 = (const float*)d_in[20];
    const float* W_l2 = (const float*)d_in[21];
    const float* b_l2 = (const float*)d_in[22];
    const float* W_l3 = (const float*)d_in[23];
    const float* b_l3 = (const float*)d_in[24];
    const float* W_l4 = (const float*)d_in[25];
    const float* b_l4 = (const float*)d_in[26];
    const float* W_l5 = (const float*)d_in[27];
    const float* b_l5 = (const float*)d_in[28];
    float* out = (float*)d_out;

    float* ctx = sym_addr(g_ctx);
    float* x1  = sym_addr(g_x1);
    float* x2  = sym_addr(g_x2);
    float* x3  = sym_addr(g_x3);
    float* x4  = sym_addr(g_x4);

    build_ctx_kernel<<<BATCH, 256>>>(state, task, action);

    dim3 block(256);
    // l1: ctx[8192,5124] @ W_l1[5124,2048]
    sgemm_bias_concat<<<dim3(2048 / 128, BATCH / 128), block>>>(
        ctx, INPUTW, nullptr, 0, W_l1, b_l1, x1, 2048);
    // l2: [x1|ctx] @ W_l2[7172,1024]
    sgemm_bias_concat<<<dim3(1024 / 128, BATCH / 128), block>>>(
        x1, 2048, ctx, INPUTW, W_l2, b_l2, x2, 1024);
    // l3: [x2|ctx] @ W_l3[6148,1024]
    sgemm_bias_concat<<<dim3(1024 / 128, BATCH / 128), block>>>(
        x2, 1024, ctx, INPUTW, W_l3, b_l3, x3, 1024);
    // l4: [x3|ctx] @ W_l4[6148,512]
    sgemm_bias_concat<<<dim3(512 / 128, BATCH / 128), block>>>(
        x3, 1024, ctx, INPUTW, W_l4, b_l4, x4, 512);
    // l5: x4[8192,512] @ W_l5[512,1024] -> out
    sgemm_bias_concat<<<dim3(1024 / 128, BATCH / 128), block>>>(
        x4, 512, nullptr, 0, W_l5, b_l5, out, 1024);
}

// round 3
// speedup vs baseline: 3.0058x; 3.0058x over previous
#include <cuda_runtime.h>
#include <cuda_bf16.h>
#include <cstdint>

// ============================================================================
// Policy_Network via mma.sync bf16 split-GEMM (legacy HMMA path; tcgen05 is
// unavailable: harness PTX targets plain sm_103, no 'a' features).
//   ctx = [state|task|action] -> [8192, 5124] padded to 5152
//   x1 = ctx @ W1 + b1   [8192,2048]
//   x2 = [x1|ctx] @ W2   [8192,1024]
//   x3 = [x2|ctx] @ W3   [8192,1024]
//   x4 = [x3|ctx] @ W4   [8192,512]
//   out= x4 @ W5 + b5    [8192,1024] fp32
// fp32 a = a_hi + a_lo (bf16); product = ah*bh + ah*bl + al*bh in fp32 acc.
// W stays in [K,N] layout (mma.row.col + ldmatrix.trans), split elementwise.
// ============================================================================

#define BATCH   8192
#define CTXP    5152            // 5124 padded to 32

typedef __nv_bfloat16 bf16;

// ---------------- device scratch (no allocation allowed) -------------------
__device__ bf16 g_ctx_h[(size_t)BATCH * CTXP];
__device__ bf16 g_ctx_l[(size_t)BATCH * CTXP];
__device__ bf16 g_x1_h[(size_t)BATCH * 2048];
__device__ bf16 g_x1_l[(size_t)BATCH * 2048];
__device__ bf16 g_x2_h[(size_t)BATCH * 1024];
__device__ bf16 g_x2_l[(size_t)BATCH * 1024];
__device__ bf16 g_x3_h[(size_t)BATCH * 1024];
__device__ bf16 g_x3_l[(size_t)BATCH * 1024];
__device__ bf16 g_x4_h[(size_t)BATCH * 512];
__device__ bf16 g_x4_l[(size_t)BATCH * 512];
// weights in original [Kpad, N] layout, bf16 hi/lo
__device__ bf16 g_w1_h[(size_t)5152 * 2048];
__device__ bf16 g_w1_l[(size_t)5152 * 2048];
__device__ bf16 g_w2_h[(size_t)7200 * 1024];
__device__ bf16 g_w2_l[(size_t)7200 * 1024];
__device__ bf16 g_w3_h[(size_t)6176 * 1024];
__device__ bf16 g_w3_l[(size_t)6176 * 1024];
__device__ bf16 g_w4_h[(size_t)6176 * 512];
__device__ bf16 g_w4_l[(size_t)6176 * 512];
__device__ bf16 g_w5_h[(size_t)512  * 1024];
__device__ bf16 g_w5_l[(size_t)512  * 1024];

// ---------------- PTX helpers ----------------------------------------------
__device__ __forceinline__ uint32_t smem_u32(const void* p) {
    uint32_t a;
    asm("{ .reg .u64 t; cvta.to.shared.u64 t, %1; cvt.u32.u64 %0, t; }"
        : "=r"(a) : "l"(p));
    return a;
}
__device__ __forceinline__ void cp16(uint32_t dst, const void* src) {
    asm volatile("cp.async.cg.shared.global [%0], [%1], 16;" :: "r"(dst), "l"(src));
}
__device__ __forceinline__ void cp_commit() {
    asm volatile("cp.async.commit_group;" ::: "memory");
}
__device__ __forceinline__ void ldsm4(uint32_t* r, uint32_t a) {
    asm volatile("ldmatrix.sync.aligned.m8n8.x4.shared.b16 {%0,%1,%2,%3}, [%4];"
        : "=r"(r[0]), "=r"(r[1]), "=r"(r[2]), "=r"(r[3]) : "r"(a));
}
__device__ __forceinline__ void ldsm4t(uint32_t* r, uint32_t a) {
    asm volatile("ldmatrix.sync.aligned.m8n8.x4.trans.shared.b16 {%0,%1,%2,%3}, [%4];"
        : "=r"(r[0]), "=r"(r[1]), "=r"(r[2]), "=r"(r[3]) : "r"(a));
}
__device__ __forceinline__ void mma16816(float* d, const uint32_t* a, const uint32_t* b) {
    asm volatile(
        "mma.sync.aligned.m16n8k16.row.col.f32.bf16.bf16.f32 "
        "{%0,%1,%2,%3}, {%4,%5,%6,%7}, {%8,%9}, {%0,%1,%2,%3};"
        : "+f"(d[0]), "+f"(d[1]), "+f"(d[2]), "+f"(d[3])
        : "r"(a[0]), "r"(a[1]), "r"(a[2]), "r"(a[3]), "r"(b[0]), "r"(b[1]));
}
__device__ __forceinline__ void split2(float v, bf16& h, bf16& l) {
    h = __float2bfloat16_rn(v);
    l = __float2bfloat16_rn(v - __bfloat162float(h));
}

// ---------------- ctx build: fp32 -> bf16 hi/lo, padded --------------------
__global__ void build_ctx(const float* __restrict__ state,
                          const float* __restrict__ task,
                          const float* __restrict__ action) {
    int r = blockIdx.x, t = threadIdx.x;
    bf16* ch = g_ctx_h + (size_t)r * CTXP;
    bf16* cl = g_ctx_l + (size_t)r * CTXP;

    const float4* s4 = reinterpret_cast<const float4*>(state + (size_t)r * 4096);
    #pragma unroll 2
    for (int i = t; i < 1024; i += 256) {
        float4 v = s4[i];
        bf16 h0,l0,h1,l1,h2,l2,h3,l3;
        split2(v.x,h0,l0); split2(v.y,h1,l1); split2(v.z,h2,l2); split2(v.w,h3,l3);
        *reinterpret_cast<__nv_bfloat162*>(ch + 4*i)     = __nv_bfloat162(h0,h1);
        *reinterpret_cast<__nv_bfloat162*>(ch + 4*i + 2) = __nv_bfloat162(h2,h3);
        *reinterpret_cast<__nv_bfloat162*>(cl + 4*i)     = __nv_bfloat162(l0,l1);
        *reinterpret_cast<__nv_bfloat162*>(cl + 4*i + 2) = __nv_bfloat162(l2,l3);
    }
    if (t < 4) {
        bf16 h,l; split2(task[(size_t)r*4 + t], h, l);
        ch[4096 + t] = h; cl[4096 + t] = l;
    }
    {
        const float4* a4 = reinterpret_cast<const float4*>(action + (size_t)r * 1024);
        float4 v = a4[t];
        bf16 h0,l0,h1,l1,h2,l2,h3,l3;
        split2(v.x,h0,l0); split2(v.y,h1,l1); split2(v.z,h2,l2); split2(v.w,h3,l3);
        int c = 4100 + 4*t;
        *reinterpret_cast<__nv_bfloat162*>(ch + c)     = __nv_bfloat162(h0,h1);
        *reinterpret_cast<__nv_bfloat162*>(ch + c + 2) = __nv_bfloat162(h2,h3);
        *reinterpret_cast<__nv_bfloat162*>(cl + c)     = __nv_bfloat162(l0,l1);
        *reinterpret_cast<__nv_bfloat162*>(cl + c + 2) = __nv_bfloat162(l2,l3);
    }
    if (t < 28) {  // zero pad 5124..5151
        bf16 z = __float2bfloat16_rn(0.0f);
        ch[5124 + t] = z; cl[5124 + t] = z;
    }
}

// ---------------- weight split (no transpose): W[Kreal,N] -> [Kpad,N] ------
// Padding rows are provably only at the tail (ctx is always the last concat
// segment), so element e is valid iff e < Kreal*N.
__global__ void split_weight(const float* __restrict__ W,
                             bf16* __restrict__ Wh, bf16* __restrict__ Wl,
                             size_t total4, size_t valid_elems) {
    size_t e = (size_t)blockIdx.x * 256 + threadIdx.x;
    if (e >= total4) return;
    size_t base = e * 4;
    float4 v = make_float4(0.f, 0.f, 0.f, 0.f);
    if (base < valid_elems) v = *reinterpret_cast<const float4*>(W + base);
    bf16 h0,l0,h1,l1,h2,l2,h3,l3;
    split2(v.x,h0,l0); split2(v.y,h1,l1); split2(v.z,h2,l2); split2(v.w,h3,l3);
    *reinterpret_cast<__nv_bfloat162*>(Wh + base)     = __nv_bfloat162(h0,h1);
    *reinterpret_cast<__nv_bfloat162*>(Wh + base + 2) = __nv_bfloat162(h2,h3);
    *reinterpret_cast<__nv_bfloat162*>(Wl + base)     = __nv_bfloat162(l0,l1);
    *reinterpret_cast<__nv_bfloat162*>(Wl + base + 2) = __nv_bfloat162(l2,l3);
}

// ---------------- HMMA split GEMM ------------------------------------------
// C[8192, N] = [A1(K1) | A2] @ W + bias.  W in [Ktot, N] bf16 hi/lo.
// CTA 128x128, BK=32, 8 warps (2x4), warp tile 64x32, double-buffered cp.async.
// smem (bytes): A hi/lo: rows stride 80 (128x32 bf16 + pad), B: stride 272.
#define A_STRIDE 80
#define B_STRIDE 272
#define ABUF     (128 * A_STRIDE)     // 10240
#define BBUF     (32 * B_STRIDE)      // 8704
#define AH_OFF   0
#define AL_OFF   (2 * ABUF)           // 20480
#define BH_OFF   (4 * ABUF)           // 40960
#define BL_OFF   (BH_OFF + 2 * BBUF)  // 58368
#define SMEM_TOT (BL_OFF + 2 * BBUF)  // 75776

__global__ __launch_bounds__(256, 2)
void gemm_hmma_split(const bf16* __restrict__ A1h, const bf16* __restrict__ A1l,
                     int sA1, int K1,
                     const bf16* __restrict__ A2h, const bf16* __restrict__ A2l,
                     int sA2, int Ktot,
                     const bf16* __restrict__ Wh, const bf16* __restrict__ Wl,
                     const float* __restrict__ bias,
                     float* __restrict__ Cf,
                     bf16* __restrict__ Ch, bf16* __restrict__ Cl,
                     int N) {
    extern __shared__ char smem_raw[];
    const uint32_t sb = smem_u32(smem_raw);

    const int tid  = threadIdx.x;
    const int wid  = tid >> 5;
    const int lane = tid & 31;
    const int warp_m = (wid & 1) * 64;
    const int warp_n = (wid >> 1) * 32;
    const int block_row = blockIdx.y * 128;
    const int block_col = blockIdx.x * 128;

    float acc[64];
    #pragma unroll
    for (int i = 0; i < 64; i++) acc[i] = 0.0f;

    const int nk = Ktot >> 5;

    auto load_chunk = [&](int buf, int k0) {
        const bf16 *ah, *al; int st, kk = k0;
        if (k0 < K1) { ah = A1h; al = A1l; st = sA1; }
        else         { ah = A2h; al = A2l; st = sA2; kk = k0 - K1; }
        #pragma unroll
        for (int i = 0; i < 2; i++) {
            int t2 = tid * 2 + i;
            // A: 512 x 16B  (row 0..127, 4 chunks of 8 bf16)
            int ar = t2 >> 2, ac = t2 & 3;
            const char* sh = (const char*)(ah + (size_t)(block_row + ar) * st + kk) + ac * 16;
            const char* sl = (const char*)(al + (size_t)(block_row + ar) * st + kk) + ac * 16;
            uint32_t da = sb + AH_OFF + buf * ABUF + ar * A_STRIDE + ac * 16;
            cp16(da, sh);
            cp16(da + AL_OFF, sl);
            // B: 512 x 16B  (row 0..31 of k, 16 chunks of 8 bf16 across n)
            int br = t2 >> 4, bc = t2 & 15;
            const char* th = (const char*)(Wh + (size_t)(k0 + br) * N + block_col) + bc * 16;
            const char* tl = (const char*)(Wl + (size_t)(k0 + br) * N + block_col) + bc * 16;
            uint32_t db = sb + BH_OFF + buf * BBUF + br * B_STRIDE + bc * 16;
            cp16(db, th);
            cp16(db + (BL_OFF - BH_OFF), tl);
        }
    };

    load_chunk(0, 0);
    cp_commit();

    const int lr = lane & 15;          // ldmatrix row
    const int lc = (lane >> 4) << 3;   // ldmatrix col half

    for (int it = 0; it < nk; ++it) {
        if (it + 1 < nk) { load_chunk((it + 1) & 1, (it + 1) << 5); cp_commit(); }
        if (it + 1 < nk) asm volatile("cp.async.wait_group 1;" ::: "memory");
        else             asm volatile("cp.async.wait_group 0;" ::: "memory");
        __syncthreads();

        const int buf = it & 1;
        const uint32_t sA = sb + AH_OFF + buf * ABUF;
        const uint32_t sB = sb + BH_OFF + buf * BBUF;

        #pragma unroll
        for (int k2 = 0; k2 < 2; k2++) {
            // B fragments: 2x ldmatrix.x4.trans cover n=0..31 (hi and lo)
            uint32_t bh[8], bl[8];
            #pragma unroll
            for (int nb = 0; nb < 2; nb++) {
                uint32_t addr = sB + (k2 * 16 + lr) * B_STRIDE
                              + (warp_n + nb * 16 + lc) * 2;
                ldsm4t(&bh[nb * 4], addr);
                ldsm4t(&bl[nb * 4], addr + (BL_OFF - BH_OFF));
            }
            #pragma unroll
            for (int mi = 0; mi < 4; mi++) {
                uint32_t ah[4], al[4];
                uint32_t addr = sA + (warp_m + mi * 16 + lr) * A_STRIDE
                              + (k2 * 16 + lc) * 2;
                ldsm4(ah, addr);
                ldsm4(al, addr + AL_OFF);
                #pragma unroll
                for (int ni = 0; ni < 4; ni++) {
                    float* d = acc + (mi * 4 + ni) * 4;
                    const uint32_t* bhf = &bh[ni * 2];
                    const uint32_t* blf = &bl[ni * 2];
                    mma16816(d, ah, bhf);
                    mma16816(d, ah, blf);
                    mma16816(d, al, bhf);
                }
            }
        }
        __syncthreads();
    }

    // ---- epilogue: regs -> gmem, +bias ----
    #pragma unroll
    for (int mi = 0; mi < 4; mi++) {
        #pragma unroll
        for (int ni = 0; ni < 4; ni++) {
            const float* d = acc + (mi * 4 + ni) * 4;
            int r0 = block_row + warp_m + mi * 16 + (lane >> 2);
            int c0 = block_col + warp_n + ni * 8 + (lane & 3) * 2;
            float bv0 = bias[c0], bv1 = bias[c0 + 1];
            float v00 = d[0] + bv0, v01 = d[1] + bv1;
            float v10 = d[2] + bv0, v11 = d[3] + bv1;
            if (Cf) {
                *reinterpret_cast<float2*>(Cf + (size_t)r0 * N + c0)       = make_float2(v00, v01);
                *reinterpret_cast<float2*>(Cf + (size_t)(r0 + 8) * N + c0) = make_float2(v10, v11);
            } else {
                bf16 h0,l0,h1,l1;
                split2(v00,h0,l0); split2(v01,h1,l1);
                *reinterpret_cast<__nv_bfloat162*>(Ch + (size_t)r0 * N + c0) = __nv_bfloat162(h0,h1);
                *reinterpret_cast<__nv_bfloat162*>(Cl + (size_t)r0 * N + c0) = __nv_bfloat162(l0,l1);
                split2(v10,h0,l0); split2(v11,h1,l1);
                *reinterpret_cast<__nv_bfloat162*>(Ch + (size_t)(r0+8) * N + c0) = __nv_bfloat162(h0,h1);
                *reinterpret_cast<__nv_bfloat162*>(Cl + (size_t)(r0+8) * N + c0) = __nv_bfloat162(l0,l1);
            }
        }
    }
}

// ---------------- host ------------------------------------------------------
template <typename T>
static T* sym_addr(const void* symbol) {
    void* p = nullptr;
    cudaGetSymbolAddress(&p, symbol);
    return reinterpret_cast<T*>(p);
}

extern "C" void kernel_launch(void* const* d_in, const int* in_sizes, int n_in,
                              void* d_out, int out_size) {
    const float* state  = (const float*)d_in[0];
    const float* action = (const float*)d_in[1];
    const float* task   = (const float*)d_in[2];
    // d_in[3..18]: dead cx branch weights
    const float* W_l1 = (const float*)d_in[19];
    const float* b_l1 = (const float*)d_in[20];
    const float* W_l2 = (const float*)d_in[21];
    const float* b_l2 = (const float*)d_in[22];
    const float* W_l3 = (const float*)d_in[23];
    const float* b_l3 = (const float*)d_in[24];
    const float* W_l4 = (const float*)d_in[25];
    const float* b_l4 = (const float*)d_in[26];
    const float* W_l5 = (const float*)d_in[27];
    const float* b_l5 = (const float*)d_in[28];
    float* out = (float*)d_out;

    static bool attr_set = false;
    if (!attr_set) {
        cudaFuncSetAttribute(gemm_hmma_split,
                             cudaFuncAttributeMaxDynamicSharedMemorySize, SMEM_TOT);
        attr_set = true;
    }

    bf16* ctxh = sym_addr<bf16>(g_ctx_h);
    bf16* ctxl = sym_addr<bf16>(g_ctx_l);
    bf16* x1h = sym_addr<bf16>(g_x1_h);  bf16* x1l = sym_addr<bf16>(g_x1_l);
    bf16* x2h = sym_addr<bf16>(g_x2_h);  bf16* x2l = sym_addr<bf16>(g_x2_l);
    bf16* x3h = sym_addr<bf16>(g_x3_h);  bf16* x3l = sym_addr<bf16>(g_x3_l);
    bf16* x4h = sym_addr<bf16>(g_x4_h);  bf16* x4l = sym_addr<bf16>(g_x4_l);
    bf16* w1h = sym_addr<bf16>(g_w1_h);  bf16* w1l = sym_addr<bf16>(g_w1_l);
    bf16* w2h = sym_addr<bf16>(g_w2_h);  bf16* w2l = sym_addr<bf16>(g_w2_l);
    bf16* w3h = sym_addr<bf16>(g_w3_h);  bf16* w3l = sym_addr<bf16>(g_w3_l);
    bf16* w4h = sym_addr<bf16>(g_w4_h);  bf16* w4l = sym_addr<bf16>(g_w4_l);
    bf16* w5h = sym_addr<bf16>(g_w5_h);  bf16* w5l = sym_addr<bf16>(g_w5_l);

    build_ctx<<<BATCH, 256>>>(state, task, action);

    auto launch_split = [&](const float* W, bf16* Wh, bf16* Wl,
                            size_t Kpad, size_t Kreal, size_t N) {
        size_t total4 = Kpad * N / 4;
        split_weight<<<(unsigned)((total4 + 255) / 256), 256>>>(W, Wh, Wl, total4, Kreal * N);
    };
    launch_split(W_l1, w1h, w1l, 5152, 5124, 2048);
    launch_split(W_l2, w2h, w2l, 7200, 7172, 1024);
    launch_split(W_l3, w3h, w3l, 6176, 6148, 1024);
    launch_split(W_l4, w4h, w4l, 6176, 6148, 512);
    launch_split(W_l5, w5h, w5l, 512,  512,  1024);

    // l1: ctx @ W1 -> x1 (bf16 split out)
    gemm_hmma_split<<<dim3(16, 64), 256, SMEM_TOT>>>(
        ctxh, ctxl, CTXP, 5152, nullptr, nullptr, 0, 5152,
        w1h, w1l, b_l1, nullptr, x1h, x1l, 2048);
    // l2: [x1|ctx] @ W2 -> x2
    gemm_hmma_split<<<dim3(8, 64), 256, SMEM_TOT>>>(
        x1h, x1l, 2048, 2048, ctxh, ctxl, CTXP, 7200,
        w2h, w2l, b_l2, nullptr, x2h, x2l, 1024);
    // l3: [x2|ctx] @ W3 -> x3
    gemm_hmma_split<<<dim3(8, 64), 256, SMEM_TOT>>>(
        x2h, x2l, 1024, 1024, ctxh, ctxl, CTXP, 6176,
        w3h, w3l, b_l3, nullptr, x3h, x3l, 1024);
    // l4: [x3|ctx] @ W4 -> x4
    gemm_hmma_split<<<dim3(4, 64), 256, SMEM_TOT>>>(
        x3h, x3l, 1024, 1024, ctxh, ctxl, CTXP, 6176,
        w4h, w4l, b_l4, nullptr, x4h, x4l, 512);
    // l5: x4 @ W5 -> out (fp32)
    gemm_hmma_split<<<dim3(8, 64), 256, SMEM_TOT>>>(
        x4h, x4l, 512, 512, nullptr, nullptr, 0, 512,
        w5h, w5l, b_l5, out, nullptr, nullptr, 1024);
}